// round 1
// baseline (speedup 1.0000x reference)
#include <cuda_runtime.h>
#include <cstdint>

// ECGGraphNetwork fused kernel (fp32, packed f32x2 FMA path)
// B=16384, 12 leads, 512 -> 256 -> 256 -> 128, mean/max pool -> (B, 256)

#define N_LEADS 12
#define GB      4                 // batch items per block
#define MROWS   (GB * N_LEADS)    // 48 rows per block
#define F_IN    512
#define HID     256
#define F_OUT   128
#define KT      32                // K chunk
#define NTHREADS 256
#define NBLOCKS  (16384 / GB)     // 4096

// ---------------- low-level helpers ----------------

__device__ __forceinline__ uint64_t pack2(float x) {
    uint64_t r; uint32_t xi = __float_as_uint(x);
    asm("mov.b64 %0, {%1, %1};" : "=l"(r) : "r"(xi));
    return r;
}

__device__ __forceinline__ void fma2(uint64_t& d, uint64_t a, uint64_t b) {
    asm("fma.rn.f32x2 %0, %1, %2, %0;" : "+l"(d) : "l"(a), "l"(b));
}

__device__ __forceinline__ void cp16(float* dst_smem, const float* src) {
    uint32_t d = (uint32_t)__cvta_generic_to_shared(dst_smem);
    asm volatile("cp.async.cg.shared.global [%0], [%1], 16;" :: "r"(d), "l"(src));
}
__device__ __forceinline__ void cp_commit() { asm volatile("cp.async.commit_group;"); }
__device__ __forceinline__ void cp_wait1()  { asm volatile("cp.async.wait_group 1;"); }
__device__ __forceinline__ void cp_wait0()  { asm volatile("cp.async.wait_group 0;"); }

// ---------------- tile prefetch (cp.async) ----------------

template<int NCOLS>
__device__ __forceinline__ void prefetch_w(float* ws, const float* __restrict__ W, int k0) {
    constexpr int C4  = NCOLS / 4;
    constexpr int TOT = KT * C4;
    for (int idx = threadIdx.x; idx < TOT; idx += NTHREADS) {
        int r = idx / C4;
        int q = idx - r * C4;
        cp16(ws + r * NCOLS + q * 4, W + (size_t)(k0 + r) * NCOLS + q * 4);
    }
}

__device__ __forceinline__ void prefetch_x(float* xs, const float* __restrict__ x,
                                           int row0, int k0) {
    constexpr int TOT = MROWS * KT / 4; // 384
    for (int idx = threadIdx.x; idx < TOT; idx += NTHREADS) {
        int r = idx >> 3;               // KT/4 = 8
        int q = idx & 7;
        cp16(xs + r * KT + q * 4, x + (size_t)(row0 + r) * F_IN + k0 + q * 4);
    }
}

// ---------------- GEMM chunk microkernels ----------------
// Thread (rg, cg): rows rg*6..rg*6+5, column pairs c = 2*cg + 64*j.
// A-operand: warp-broadcast LDS; B-operand: conflict-free LDS.64.

__device__ __forceinline__ void gemm_chunk4(const float* __restrict__ A, int lda,
                                            const float* __restrict__ Wsm,
                                            int rg, int cg, uint64_t acc[6][4]) {
    #pragma unroll 8
    for (int k = 0; k < KT; k++) {
        const float* wk = Wsm + k * HID + 2 * cg;
        uint64_t bv0 = *(const uint64_t*)(wk);
        uint64_t bv1 = *(const uint64_t*)(wk + 64);
        uint64_t bv2 = *(const uint64_t*)(wk + 128);
        uint64_t bv3 = *(const uint64_t*)(wk + 192);
        #pragma unroll
        for (int i = 0; i < 6; i++) {
            uint64_t av = pack2(A[(rg * 6 + i) * lda + k]);
            fma2(acc[i][0], av, bv0);
            fma2(acc[i][1], av, bv1);
            fma2(acc[i][2], av, bv2);
            fma2(acc[i][3], av, bv3);
        }
    }
}

__device__ __forceinline__ void gemm_chunk2(const float* __restrict__ A, int lda,
                                            const float* __restrict__ Wsm,
                                            int rg, int cg, uint64_t acc[6][2]) {
    #pragma unroll 8
    for (int k = 0; k < KT; k++) {
        const float* wk = Wsm + k * F_OUT + 2 * cg;
        uint64_t bv0 = *(const uint64_t*)(wk);
        uint64_t bv1 = *(const uint64_t*)(wk + 64);
        #pragma unroll
        for (int i = 0; i < 6; i++) {
            uint64_t av = pack2(A[(rg * 6 + i) * lda + k]);
            fma2(acc[i][0], av, bv0);
            fma2(acc[i][1], av, bv1);
        }
    }
}

// ---------------- graph mix + bias (+ relu) ----------------
// dst[row] = sum_m A[n(row), m] * src[batchbase + m] + bias ; optional relu.

template<int COLS, bool RELU>
__device__ __forceinline__ void mix_bias(const float* __restrict__ src,
                                         float* __restrict__ dst,
                                         const float* __restrict__ Amat,
                                         const float* __restrict__ bias) {
    constexpr int C4 = COLS / 4;
    for (int idx = threadIdx.x; idx < MROWS * C4; idx += NTHREADS) {
        int r  = idx / C4;
        int c4 = idx - r * C4;
        int n  = r % N_LEADS;
        const float* sp = src + (r - n) * COLS + c4 * 4;
        float4 s = *(const float4*)(bias + c4 * 4);
        #pragma unroll
        for (int m = 0; m < N_LEADS; m++) {
            float a  = Amat[n * N_LEADS + m];
            float4 v = *(const float4*)(sp + m * COLS);
            s.x = fmaf(a, v.x, s.x);
            s.y = fmaf(a, v.y, s.y);
            s.z = fmaf(a, v.z, s.z);
            s.w = fmaf(a, v.w, s.w);
        }
        if (RELU) {
            s.x = fmaxf(s.x, 0.f); s.y = fmaxf(s.y, 0.f);
            s.z = fmaxf(s.z, 0.f); s.w = fmaxf(s.w, 0.f);
        }
        *(float4*)(dst + r * COLS + c4 * 4) = s;
    }
}

// ---------------- fused kernel ----------------

__global__ void __launch_bounds__(NTHREADS, 1)
ecg_fused(const float* __restrict__ x,
          const float* __restrict__ W1, const float* __restrict__ b1,
          const float* __restrict__ W2, const float* __restrict__ b2,
          const float* __restrict__ W3, const float* __restrict__ b3,
          float* __restrict__ out)
{
    extern __shared__ float sm[];
    float* Xs0  = sm;                          // MROWS*KT = 1536 floats
    float* Xs1  = Xs0 + MROWS * KT;
    float* Ws0  = Xs1 + MROWS * KT;            // KT*HID = 8192 floats
    float* Ws1  = Ws0 + KT * HID;
    float* buf0 = Ws1 + KT * HID;              // MROWS*HID = 12288
    float* buf1 = buf0 + MROWS * HID;          // 12288
    float* Amat = buf1 + MROWS * HID;          // 144

    const int tid  = threadIdx.x;
    const int rg   = tid >> 5;                 // 0..7
    const int cg   = tid & 31;                 // 0..31
    const int row0 = blockIdx.x * MROWS;       // row into (B*12, F_IN)

    // Build normalized adjacency (A_eff = adj + 2I, D^{-1/2} A_eff D^{-1/2})
    if (tid < N_LEADS * N_LEADS) {
        const unsigned char ci[15] = {0,0,1,0,1,2,0,1,1,2,6,7,8,9,10};
        const unsigned char cj[15] = {1,2,2,3,3,3,4,4,5,5,7,8,9,10,11};
        int i = tid / N_LEADS;
        int j = tid - i * N_LEADS;
        float a = (i == j) ? 2.0f : 0.0f;
        float degi = 2.0f, degj = 2.0f;
        #pragma unroll
        for (int e = 0; e < 15; e++) {
            int u = ci[e], v = cj[e];
            if ((u == i && v == j) || (u == j && v == i)) a = 1.0f;
            if (u == i || v == i) degi += 1.0f;
            if (u == j || v == j) degj += 1.0f;
        }
        Amat[tid] = a * rsqrtf(degi) * rsqrtf(degj);
    }

    uint64_t acc[6][4];

    // ================= Stage 1: X @ W1 (K = 512) =================
    #pragma unroll
    for (int i = 0; i < 6; i++)
        #pragma unroll
        for (int j = 0; j < 4; j++) acc[i][j] = 0ull;

    prefetch_x(Xs0, x, row0, 0);
    prefetch_w<HID>(Ws0, W1, 0);
    cp_commit();
    {
        constexpr int NC = F_IN / KT; // 16
        int s = 0;
        for (int c = 0; c < NC; c++) {
            float* xc = s ? Xs1 : Xs0;
            float* wc = s ? Ws1 : Ws0;
            if (c + 1 < NC) {
                float* xn = s ? Xs0 : Xs1;
                float* wn = s ? Ws0 : Ws1;
                prefetch_x(xn, x, row0, (c + 1) * KT);
                prefetch_w<HID>(wn, W1, (c + 1) * KT);
                cp_commit();
                cp_wait1();
            } else {
                cp_wait0();
            }
            __syncthreads();
            gemm_chunk4(xc, KT, wc, rg, cg, acc);
            __syncthreads();
            s ^= 1;
        }
    }
    #pragma unroll
    for (int i = 0; i < 6; i++)
        #pragma unroll
        for (int j = 0; j < 4; j++)
            *(uint64_t*)(buf0 + (rg * 6 + i) * HID + 2 * cg + 64 * j) = acc[i][j];
    __syncthreads();
    mix_bias<HID, true>(buf0, buf1, Amat, b1);
    __syncthreads();

    // ================= Stage 2: H1 @ W2 (K = 256) =================
    #pragma unroll
    for (int i = 0; i < 6; i++)
        #pragma unroll
        for (int j = 0; j < 4; j++) acc[i][j] = 0ull;

    prefetch_w<HID>(Ws0, W2, 0);
    cp_commit();
    {
        constexpr int NC = HID / KT; // 8
        int s = 0;
        for (int c = 0; c < NC; c++) {
            float* wc = s ? Ws1 : Ws0;
            if (c + 1 < NC) {
                float* wn = s ? Ws0 : Ws1;
                prefetch_w<HID>(wn, W2, (c + 1) * KT);
                cp_commit();
                cp_wait1();
            } else {
                cp_wait0();
            }
            __syncthreads();
            gemm_chunk4(buf1 + c * KT, HID, wc, rg, cg, acc);
            __syncthreads();
            s ^= 1;
        }
    }
    #pragma unroll
    for (int i = 0; i < 6; i++)
        #pragma unroll
        for (int j = 0; j < 4; j++)
            *(uint64_t*)(buf0 + (rg * 6 + i) * HID + 2 * cg + 64 * j) = acc[i][j];
    __syncthreads();
    mix_bias<HID, true>(buf0, buf1, Amat, b2);
    __syncthreads();

    // ================= Stage 3: H2 @ W3 (K = 256, N = 128) =================
    uint64_t acc3[6][2];
    #pragma unroll
    for (int i = 0; i < 6; i++) { acc3[i][0] = 0ull; acc3[i][1] = 0ull; }

    prefetch_w<F_OUT>(Ws0, W3, 0);
    cp_commit();
    {
        constexpr int NC = HID / KT; // 8
        int s = 0;
        for (int c = 0; c < NC; c++) {
            float* wc = s ? Ws1 : Ws0;
            if (c + 1 < NC) {
                float* wn = s ? Ws0 : Ws1;
                prefetch_w<F_OUT>(wn, W3, (c + 1) * KT);
                cp_commit();
                cp_wait1();
            } else {
                cp_wait0();
            }
            __syncthreads();
            gemm_chunk2(buf1 + c * KT, HID, wc, rg, cg, acc3);
            __syncthreads();
            s ^= 1;
        }
    }
    #pragma unroll
    for (int i = 0; i < 6; i++) {
        *(uint64_t*)(buf0 + (rg * 6 + i) * F_OUT + 2 * cg)      = acc3[i][0];
        *(uint64_t*)(buf0 + (rg * 6 + i) * F_OUT + 2 * cg + 64) = acc3[i][1];
    }
    __syncthreads();
    mix_bias<F_OUT, false>(buf0, buf1, Amat, b3);
    __syncthreads();

    // ================= Pool: mean + max over 12 leads =================
    const int bout0 = blockIdx.x * GB;
    for (int idx = tid; idx < GB * (F_OUT / 4); idx += NTHREADS) {
        int b  = idx >> 5;              // F_OUT/4 = 32
        int c4 = idx & 31;
        const float* p = buf1 + (b * N_LEADS) * F_OUT + c4 * 4;
        float4 v   = *(const float4*)p;
        float4 sum = v;
        float4 mx  = v;
        #pragma unroll
        for (int m = 1; m < N_LEADS; m++) {
            float4 w = *(const float4*)(p + m * F_OUT);
            sum.x += w.x; sum.y += w.y; sum.z += w.z; sum.w += w.w;
            mx.x = fmaxf(mx.x, w.x); mx.y = fmaxf(mx.y, w.y);
            mx.z = fmaxf(mx.z, w.z); mx.w = fmaxf(mx.w, w.w);
        }
        const float inv = 1.0f / 12.0f;
        float4 mean = make_float4(sum.x * inv, sum.y * inv, sum.z * inv, sum.w * inv);
        float* op = out + (size_t)(bout0 + b) * (2 * F_OUT);
        *(float4*)(op + c4 * 4)         = mean;
        *(float4*)(op + F_OUT + c4 * 4) = mx;
    }
}

// ---------------- launch ----------------

extern "C" void kernel_launch(void* const* d_in, const int* in_sizes, int n_in,
                              void* d_out, int out_size)
{
    const float* x  = (const float*)d_in[0];
    const float* W1 = (const float*)d_in[1];
    const float* b1 = (const float*)d_in[2];
    const float* W2 = (const float*)d_in[3];
    const float* b2 = (const float*)d_in[4];
    const float* W3 = (const float*)d_in[5];
    const float* b3 = (const float*)d_in[6];
    float* out = (float*)d_out;

    const int smem_bytes =
        (2 * MROWS * KT + 2 * KT * HID + 2 * MROWS * HID + 144) * (int)sizeof(float);

    cudaFuncSetAttribute((const void*)ecg_fused,
                         cudaFuncAttributeMaxDynamicSharedMemorySize, smem_bytes);

    ecg_fused<<<NBLOCKS, NTHREADS, smem_bytes>>>(x, W1, b1, W2, b2, W3, b3, out);
}

// round 3
// speedup vs baseline: 1.9714x; 1.9714x over previous
#include <cuda_runtime.h>
#include <cuda_bf16.h>
#include <cstdint>

// ECGGraphNetwork, fully fused, bf16 mma.sync (HMMA) with 3-term split.
// Per block: 8 batch items (96 rows). Layers 512->256->256->128, graph-mix
// between layers in smem, mean/max pool at the end. No global intermediates.

#define BATCH    16384
#define NLEADS   12
#define MROWS    96                 // 8 items * 12 leads
#define NTHREADS 256
#define NBLOCKS  (BATCH / 8)        // 2048

#define LDW   264                   // W chunk row stride (bf16 elems), 528B
#define LDAX  40                    // X chunk row stride (bf16 elems), 80B
#define LDH   264                   // H row stride (bf16 elems), 528B
#define OUTLD 264                   // OUT row stride (fp32 elems), 1056B

// smem byte offsets
#define WCH      16896              // one W term buffer: 32*528
#define OFFX     67584              // after 4 W buffers
#define XCH      7680               // one X term buffer: 96*80
#define OFF_OUT  0                  // aliases chunk region (96*264*4 = 101376)
#define OFF_HH   101376
#define OFF_HL   152064             // +96*528
#define OFF_ADJ  202752
#define SMEMSZ   203328

// ---------------- PTX helpers ----------------

__device__ __forceinline__ uint32_t smem_u32(const void* p) {
    uint32_t a;
    asm("{ .reg .u64 t; cvta.to.shared.u64 t, %1; cvt.u32.u64 %0, t; }" : "=r"(a) : "l"(p));
    return a;
}

__device__ __forceinline__ void ldsm4(uint32_t* r, uint32_t a) {
    asm volatile("ldmatrix.sync.aligned.m8n8.x4.shared.b16 {%0,%1,%2,%3}, [%4];"
                 : "=r"(r[0]), "=r"(r[1]), "=r"(r[2]), "=r"(r[3]) : "r"(a));
}
__device__ __forceinline__ void ldsm4t(uint32_t* r, uint32_t a) {
    asm volatile("ldmatrix.sync.aligned.m8n8.x4.trans.shared.b16 {%0,%1,%2,%3}, [%4];"
                 : "=r"(r[0]), "=r"(r[1]), "=r"(r[2]), "=r"(r[3]) : "r"(a));
}

__device__ __forceinline__ void mma_bf16(float* d, const uint32_t* a,
                                         uint32_t b0, uint32_t b1) {
    asm volatile(
        "mma.sync.aligned.m16n8k16.row.col.f32.bf16.bf16.f32 "
        "{%0,%1,%2,%3}, {%4,%5,%6,%7}, {%8,%9}, {%0,%1,%2,%3};"
        : "+f"(d[0]), "+f"(d[1]), "+f"(d[2]), "+f"(d[3])
        : "r"(a[0]), "r"(a[1]), "r"(a[2]), "r"(a[3]), "r"(b0), "r"(b1));
}

// fp32 -> (bf16 hi, bf16 lo) split
__device__ __forceinline__ void bsplit(float x, uint32_t& h, uint32_t& l) {
    __nv_bfloat16 hb = __float2bfloat16(x);
    h = (uint32_t)__bfloat16_as_ushort(hb);
    float lf = x - __bfloat162float(hb);
    l = (uint32_t)__bfloat16_as_ushort(__float2bfloat16(lf));
}
__device__ __forceinline__ void split4(float4 v, uint2& hv, uint2& lv) {
    uint32_t h0, h1, h2, h3, l0, l1, l2, l3;
    bsplit(v.x, h0, l0); bsplit(v.y, h1, l1);
    bsplit(v.z, h2, l2); bsplit(v.w, h3, l3);
    hv.x = h0 | (h1 << 16); hv.y = h2 | (h3 << 16);
    lv.x = l0 | (l1 << 16); lv.y = l2 | (l3 << 16);
}

// ---------------- adjacency ----------------
__device__ __forceinline__ void build_adj(float* As, int tid) {
    if (tid < NLEADS * NLEADS) {
        const unsigned char ci[15] = {0,0,1,0,1,2,0,1,1,2,6,7,8,9,10};
        const unsigned char cj[15] = {1,2,2,3,3,3,4,4,5,5,7,8,9,10,11};
        int i = tid / NLEADS;
        int j = tid - i * NLEADS;
        float a = (i == j) ? 2.0f : 0.0f;
        float degi = 2.0f, degj = 2.0f;
        #pragma unroll
        for (int e = 0; e < 15; e++) {
            int u = ci[e], v = cj[e];
            if ((u == i && v == j) || (u == j && v == i)) a = 1.0f;
            if (u == i || v == i) degi += 1.0f;
            if (u == j || v == j) degj += 1.0f;
        }
        As[tid] = a * rsqrtf(degi) * rsqrtf(degj);
    }
}

// ---------------- k-step: 6 m-tiles x NT n-tiles x 3 split MMAs ----------------
template<int NT>
__device__ __forceinline__ void kstep_mma(float (*acc)[NT][4],
                                          uint32_t aHi, uint32_t aLo, int ldaB,
                                          uint32_t wHi, uint32_t wLo, int lane)
{
    uint32_t bh[2 * NT], bl[2 * NT];
    {
        uint32_t off = (uint32_t)((lane & 15) * (LDW * 2)) + (uint32_t)(((lane >> 4) << 3) * 2);
        ldsm4t(bh, wHi + off);
        if (NT == 4) ldsm4t(bh + 4, wHi + off + 32);
        ldsm4t(bl, wLo + off);
        if (NT == 4) ldsm4t(bl + 4, wLo + off + 32);
    }
    uint32_t aoff = (uint32_t)((lane & 15) * ldaB) + (uint32_t)(((lane >> 4) << 3) * 2);
    #pragma unroll
    for (int m = 0; m < 6; m++) {
        uint32_t ah[4], al[4];
        ldsm4(ah, aHi + (uint32_t)(m * 16 * ldaB) + aoff);
        #pragma unroll
        for (int n = 0; n < NT; n++) mma_bf16(acc[m][n], ah, bh[2*n], bh[2*n+1]);
        #pragma unroll
        for (int n = 0; n < NT; n++) mma_bf16(acc[m][n], ah, bl[2*n], bl[2*n+1]);
        ldsm4(al, aLo + (uint32_t)(m * 16 * ldaB) + aoff);
        #pragma unroll
        for (int n = 0; n < NT; n++) mma_bf16(acc[m][n], al, bh[2*n], bh[2*n+1]);
    }
}

// ---------------- one GEMM layer: OUT = A @ W (fp32 result in smem) ----------------
template<int KD, int ND, bool L1>
__device__ __forceinline__ void gemm_layer(char* smem, uint32_t sbase,
                                           const float* __restrict__ Asrc,
                                           const float* __restrict__ W, int row0)
{
    constexpr int NC = KD / 32;
    constexpr int NT = ND / 64;        // n8-tiles per warp (4 or 2)
    constexpr int NW = ND / 32;        // float4s of W per thread per chunk
    const int tid = threadIdx.x, wid = tid >> 5, lane = tid & 31;
    const int n0 = wid * (ND / 8);

    float acc[6][NT][4];
    #pragma unroll
    for (int m = 0; m < 6; m++)
        #pragma unroll
        for (int n = 0; n < NT; n++)
            #pragma unroll
            for (int q = 0; q < 4; q++) acc[m][n][q] = 0.0f;

    float4 wr[NW];
    float4 xr[3];

    // preload chunk 0
    #pragma unroll
    for (int i = 0; i < NW; i++)
        wr[i] = *(const float4*)(W + (size_t)(tid + i * 256) * 4);
    if (L1) {
        #pragma unroll
        for (int i = 0; i < 3; i++) {
            int f4 = tid + i * 256;
            xr[i] = *(const float4*)(Asrc + (size_t)(row0 + (f4 >> 3)) * 512 + (f4 & 7) * 4);
        }
    }

    for (int c = 0; c < NC; c++) {
        const int buf = c & 1;
        // ---- convert + store current chunk ----
        {
            char* wb_h = smem + (buf * 2 + 0) * WCH;
            char* wb_l = smem + (buf * 2 + 1) * WCH;
            #pragma unroll
            for (int i = 0; i < NW; i++) {
                int f4  = tid + i * 256;
                int row = f4 / (ND / 4), c4 = f4 % (ND / 4);
                uint2 hv, lv;
                split4(wr[i], hv, lv);
                int off = row * (LDW * 2) + c4 * 8;
                *(uint2*)(wb_h + off) = hv;
                *(uint2*)(wb_l + off) = lv;
            }
            if (L1) {
                char* xb_h = smem + OFFX + (buf * 2 + 0) * XCH;
                char* xb_l = smem + OFFX + (buf * 2 + 1) * XCH;
                #pragma unroll
                for (int i = 0; i < 3; i++) {
                    int f4 = tid + i * 256;
                    uint2 hv, lv;
                    split4(xr[i], hv, lv);
                    int off = (f4 >> 3) * (LDAX * 2) + (f4 & 7) * 8;
                    *(uint2*)(xb_h + off) = hv;
                    *(uint2*)(xb_l + off) = lv;
                }
            }
        }
        __syncthreads();
        // ---- prefetch next chunk into regs ----
        if (c + 1 < NC) {
            const float* Wn = W + (size_t)(c + 1) * 32 * ND;
            #pragma unroll
            for (int i = 0; i < NW; i++)
                wr[i] = *(const float4*)(Wn + (size_t)(tid + i * 256) * 4);
            if (L1) {
                #pragma unroll
                for (int i = 0; i < 3; i++) {
                    int f4 = tid + i * 256;
                    xr[i] = *(const float4*)(Asrc + (size_t)(row0 + (f4 >> 3)) * 512
                                             + (c + 1) * 32 + (f4 & 7) * 4);
                }
            }
        }
        // ---- compute 2 k-steps of 16 ----
        #pragma unroll
        for (int st = 0; st < 2; st++) {
            uint32_t wh = sbase + (uint32_t)((buf * 2 + 0) * WCH + st * 16 * (LDW * 2) + n0 * 2);
            uint32_t wl = sbase + (uint32_t)((buf * 2 + 1) * WCH + st * 16 * (LDW * 2) + n0 * 2);
            if (L1) {
                uint32_t ah = sbase + (uint32_t)(OFFX + (buf * 2) * XCH + st * 32);
                kstep_mma<NT>(acc, ah, ah + XCH, LDAX * 2, wh, wl, lane);
            } else {
                int kg = c * 32 + st * 16;
                uint32_t ah = sbase + (uint32_t)(OFF_HH + kg * 2);
                uint32_t al = sbase + (uint32_t)(OFF_HL + kg * 2);
                kstep_mma<NT>(acc, ah, al, LDH * 2, wh, wl, lane);
            }
        }
        __syncthreads();
    }

    // ---- epilogue: accum -> OUT (fp32, stride OUTLD) ----
    float* OUT = (float*)(smem + OFF_OUT);
    #pragma unroll
    for (int m = 0; m < 6; m++)
        #pragma unroll
        for (int n = 0; n < NT; n++) {
            int r = m * 16 + (lane >> 2);
            int cc = n0 + n * 8 + (lane & 3) * 2;
            *(float2*)(OUT + r * OUTLD + cc)       = make_float2(acc[m][n][0], acc[m][n][1]);
            *(float2*)(OUT + (r + 8) * OUTLD + cc) = make_float2(acc[m][n][2], acc[m][n][3]);
        }
    __syncthreads();
}

// ---------------- mix + relu + bf16 re-split (N=256) ----------------
__device__ __forceinline__ void mix_relu(char* smem, const float* __restrict__ bias) {
    const float* As  = (const float*)(smem + OFF_ADJ);
    const float* OUT = (const float*)(smem + OFF_OUT);
    for (int idx = threadIdx.x; idx < MROWS * 64; idx += NTHREADS) {
        int r  = idx >> 6;
        int c4 = idx & 63;
        int n  = r % NLEADS;
        int rb = r - n;
        float4 s = *(const float4*)(bias + c4 * 4);
        #pragma unroll
        for (int m = 0; m < NLEADS; m++) {
            float a  = As[n * NLEADS + m];
            float4 v = *(const float4*)(OUT + (rb + m) * OUTLD + c4 * 4);
            s.x = fmaf(a, v.x, s.x); s.y = fmaf(a, v.y, s.y);
            s.z = fmaf(a, v.z, s.z); s.w = fmaf(a, v.w, s.w);
        }
        s.x = fmaxf(s.x, 0.f); s.y = fmaxf(s.y, 0.f);
        s.z = fmaxf(s.z, 0.f); s.w = fmaxf(s.w, 0.f);
        uint2 hv, lv;
        split4(s, hv, lv);
        int off = r * (LDH * 2) + c4 * 8;
        *(uint2*)(smem + OFF_HH + off) = hv;
        *(uint2*)(smem + OFF_HL + off) = lv;
    }
}

// ---------------- layer-3 mix + bias + mean/max pool ----------------
__device__ __forceinline__ void mix_pool(char* smem, const float* __restrict__ bias,
                                         float* __restrict__ out, int bout0) {
    const float* As  = (const float*)(smem + OFF_ADJ);
    const float* OUT = (const float*)(smem + OFF_OUT);
    int b  = threadIdx.x >> 5;      // 0..7
    int c4 = threadIdx.x & 31;      // 0..31 (128/4)
    float4 v[NLEADS];
    #pragma unroll
    for (int m = 0; m < NLEADS; m++)
        v[m] = *(const float4*)(OUT + (b * NLEADS + m) * OUTLD + c4 * 4);
    float4 bv = *(const float4*)(bias + c4 * 4);
    float4 sum = make_float4(0.f, 0.f, 0.f, 0.f);
    float4 mx  = make_float4(-3.4e38f, -3.4e38f, -3.4e38f, -3.4e38f);
    #pragma unroll
    for (int r = 0; r < NLEADS; r++) {
        float4 s = bv;
        #pragma unroll
        for (int m = 0; m < NLEADS; m++) {
            float a = As[r * NLEADS + m];
            s.x = fmaf(a, v[m].x, s.x); s.y = fmaf(a, v[m].y, s.y);
            s.z = fmaf(a, v[m].z, s.z); s.w = fmaf(a, v[m].w, s.w);
        }
        sum.x += s.x; sum.y += s.y; sum.z += s.z; sum.w += s.w;
        mx.x = fmaxf(mx.x, s.x); mx.y = fmaxf(mx.y, s.y);
        mx.z = fmaxf(mx.z, s.z); mx.w = fmaxf(mx.w, s.w);
    }
    const float inv = 1.0f / 12.0f;
    float* op = out + (size_t)(bout0 + b) * 256;
    *(float4*)(op + c4 * 4)       = make_float4(sum.x*inv, sum.y*inv, sum.z*inv, sum.w*inv);
    *(float4*)(op + 128 + c4 * 4) = mx;
}

// ---------------- kernel ----------------
__global__ void __launch_bounds__(NTHREADS, 1)
ecg_mma(const float* __restrict__ x,
        const float* __restrict__ W1, const float* __restrict__ b1,
        const float* __restrict__ W2, const float* __restrict__ b2,
        const float* __restrict__ W3, const float* __restrict__ b3,
        float* __restrict__ out)
{
    extern __shared__ char smem[];
    const uint32_t sbase = smem_u32(smem);
    const int row0  = blockIdx.x * MROWS;
    const int bout0 = blockIdx.x * 8;

    build_adj((float*)(smem + OFF_ADJ), threadIdx.x);

    // layer 1: X(96x512) @ W1(512x256)
    gemm_layer<512, 256, true>(smem, sbase, x, W1, row0);
    mix_relu(smem, b1);
    __syncthreads();
    // layer 2: H(96x256) @ W2(256x256)
    gemm_layer<256, 256, false>(smem, sbase, nullptr, W2, row0);
    mix_relu(smem, b2);
    __syncthreads();
    // layer 3: H(96x256) @ W3(256x128) + mix + pool
    gemm_layer<256, 128, false>(smem, sbase, nullptr, W3, row0);
    mix_pool(smem, b3, out, bout0);
}

// ---------------- launch ----------------
extern "C" void kernel_launch(void* const* d_in, const int* in_sizes, int n_in,
                              void* d_out, int out_size)
{
    const float* x  = (const float*)d_in[0];
    const float* W1 = (const float*)d_in[1];
    const float* b1 = (const float*)d_in[2];
    const float* W2 = (const float*)d_in[3];
    const float* b2 = (const float*)d_in[4];
    const float* W3 = (const float*)d_in[5];
    const float* b3 = (const float*)d_in[6];
    float* out = (float*)d_out;

    cudaFuncSetAttribute((const void*)ecg_mma,
                         cudaFuncAttributeMaxDynamicSharedMemorySize, SMEMSZ);
    ecg_mma<<<NBLOCKS, NTHREADS, SMEMSZ>>>(x, W1, b1, W2, b2, W3, b3, out);
}